// round 1
// baseline (speedup 1.0000x reference)
#include <cuda_runtime.h>
#include <math.h>

// ---------------- scratch (static device globals; no allocations) ----------------
#define NTOK   16384            // 4 * 4096
#define DM     512
#define DFF    2048
#define SQ     4096
#define NB     4

__device__ float g_Q  [NTOK * DM];
__device__ float g_K  [NTOK * DM];
__device__ float g_V  [NTOK * DM];
__device__ float g_S  [67108864];   // 4 * 4096 * 4096
__device__ float g_att[NTOK * DM];  // also reused for ffn output
__device__ float g_x1 [NTOK * DM];
__device__ float g_h  [NTOK * DFF];

// ---------------- generic 128x128x16 SGEMM ----------------
// C[M,N] = alpha * A[M,K] * op(B) + bias ; op(B)=B[K,N] (NN) or B[N,K]^T (NT)
// M,N multiples of 128; K multiple of 16. Batched via blockIdx.z strides.
template<bool TRANS_B, bool RELU, bool HAS_BIAS>
__global__ __launch_bounds__(256)
void gemm128(const float* __restrict__ A, const float* __restrict__ B,
             const float* __restrict__ bias, float* __restrict__ C,
             int M, int N, int K, float alpha,
             long long sA, long long sB, long long sC)
{
    const int BM = 128, BN = 128, BK = 16;
    __shared__ float As[BK][BM];
    __shared__ float Bs[BK][BN];

    A += (long long)blockIdx.z * sA;
    B += (long long)blockIdx.z * sB;
    C += (long long)blockIdx.z * sC;

    const int tid = threadIdx.x;
    const int tx  = tid & 15;
    const int ty  = tid >> 4;
    const int rowBase = blockIdx.y * BM;
    const int colBase = blockIdx.x * BN;

    float acc[8][8];
    #pragma unroll
    for (int i = 0; i < 8; ++i)
        #pragma unroll
        for (int j = 0; j < 8; ++j) acc[i][j] = 0.f;

    for (int k0 = 0; k0 < K; k0 += BK) {
        // ---- load A tile: 128x16, transposed into As[k][m]
        #pragma unroll
        for (int it = 0; it < 2; ++it) {
            int idx = tid + it * 256;           // 0..511
            int r   = idx >> 2;                 // 0..127
            int kq  = idx & 3;                  // 0..3
            float4 v = *(const float4*)(A + (long long)(rowBase + r) * K + k0 + kq * 4);
            As[kq * 4 + 0][r] = v.x;
            As[kq * 4 + 1][r] = v.y;
            As[kq * 4 + 2][r] = v.z;
            As[kq * 4 + 3][r] = v.w;
        }
        // ---- load B tile into Bs[k][n]
        if (!TRANS_B) {
            #pragma unroll
            for (int it = 0; it < 2; ++it) {
                int idx = tid + it * 256;
                int kk  = idx >> 5;             // 0..15
                int nq  = idx & 31;             // 0..31
                float4 v = *(const float4*)(B + (long long)(k0 + kk) * N + colBase + nq * 4);
                *(float4*)&Bs[kk][nq * 4] = v;
            }
        } else {
            #pragma unroll
            for (int it = 0; it < 2; ++it) {
                int idx = tid + it * 256;
                int n   = idx >> 2;             // 0..127
                int kq  = idx & 3;
                float4 v = *(const float4*)(B + (long long)(colBase + n) * K + k0 + kq * 4);
                Bs[kq * 4 + 0][n] = v.x;
                Bs[kq * 4 + 1][n] = v.y;
                Bs[kq * 4 + 2][n] = v.z;
                Bs[kq * 4 + 3][n] = v.w;
            }
        }
        __syncthreads();

        #pragma unroll
        for (int kk = 0; kk < BK; ++kk) {
            float a[8], b[8];
            *(float4*)&a[0] = *(const float4*)&As[kk][ty * 8];
            *(float4*)&a[4] = *(const float4*)&As[kk][ty * 8 + 4];
            *(float4*)&b[0] = *(const float4*)&Bs[kk][tx * 8];
            *(float4*)&b[4] = *(const float4*)&Bs[kk][tx * 8 + 4];
            #pragma unroll
            for (int i = 0; i < 8; ++i)
                #pragma unroll
                for (int j = 0; j < 8; ++j)
                    acc[i][j] += a[i] * b[j];
        }
        __syncthreads();
    }

    // ---- epilogue
    #pragma unroll
    for (int i = 0; i < 8; ++i) {
        int r = rowBase + ty * 8 + i;
        #pragma unroll
        for (int j = 0; j < 8; j += 4) {
            int c = colBase + tx * 8 + j;
            float4 o;
            o.x = acc[i][j + 0] * alpha;
            o.y = acc[i][j + 1] * alpha;
            o.z = acc[i][j + 2] * alpha;
            o.w = acc[i][j + 3] * alpha;
            if (HAS_BIAS) {
                float4 bv = *(const float4*)(bias + c);
                o.x += bv.x; o.y += bv.y; o.z += bv.z; o.w += bv.w;
            }
            if (RELU) {
                o.x = fmaxf(o.x, 0.f); o.y = fmaxf(o.y, 0.f);
                o.z = fmaxf(o.z, 0.f); o.w = fmaxf(o.w, 0.f);
            }
            *(float4*)(C + (long long)r * N + c) = o;
        }
    }
}

// ---------------- softmax over rows of length 4096 ----------------
__global__ __launch_bounds__(256)
void softmax4096(float* __restrict__ S)
{
    const int N4 = SQ / 4; // 1024 float4 per row
    float4* p = (float4*)(S + (long long)blockIdx.x * SQ);
    const int tid = threadIdx.x;

    float4 v[4];
    float mx = -1e30f;
    #pragma unroll
    for (int i = 0; i < 4; ++i) {
        v[i] = p[i * 256 + tid];
        mx = fmaxf(mx, fmaxf(fmaxf(v[i].x, v[i].y), fmaxf(v[i].z, v[i].w)));
    }
    // block max reduce
    __shared__ float sh[8];
    #pragma unroll
    for (int o = 16; o > 0; o >>= 1) mx = fmaxf(mx, __shfl_xor_sync(~0u, mx, o));
    if ((tid & 31) == 0) sh[tid >> 5] = mx;
    __syncthreads();
    mx = sh[0];
    #pragma unroll
    for (int w = 1; w < 8; ++w) mx = fmaxf(mx, sh[w]);
    __syncthreads();

    float sum = 0.f;
    #pragma unroll
    for (int i = 0; i < 4; ++i) {
        v[i].x = __expf(v[i].x - mx);
        v[i].y = __expf(v[i].y - mx);
        v[i].z = __expf(v[i].z - mx);
        v[i].w = __expf(v[i].w - mx);
        sum += v[i].x + v[i].y + v[i].z + v[i].w;
    }
    #pragma unroll
    for (int o = 16; o > 0; o >>= 1) sum += __shfl_xor_sync(~0u, sum, o);
    if ((tid & 31) == 0) sh[tid >> 5] = sum;
    __syncthreads();
    sum = 0.f;
    #pragma unroll
    for (int w = 0; w < 8; ++w) sum += sh[w];
    float inv = 1.f / sum;

    #pragma unroll
    for (int i = 0; i < 4; ++i) {
        v[i].x *= inv; v[i].y *= inv; v[i].z *= inv; v[i].w *= inv;
        p[i * 256 + tid] = v[i];
    }
    (void)N4;
}

// ---------------- fused residual add + LayerNorm over 512 ----------------
__global__ __launch_bounds__(128)
void add_ln512(const float* __restrict__ X, const float* __restrict__ R,
               const float* __restrict__ g, const float* __restrict__ b,
               float* __restrict__ Y)
{
    const int tid = threadIdx.x;              // 128 threads * float4 = 512
    const long long base = (long long)blockIdx.x * DM;
    float4 v = *(const float4*)(X + base + tid * 4);
    float4 r = *(const float4*)(R + base + tid * 4);
    v.x += r.x; v.y += r.y; v.z += r.z; v.w += r.w;

    __shared__ float shm[4], shv[4];
    float s = v.x + v.y + v.z + v.w;
    #pragma unroll
    for (int o = 16; o > 0; o >>= 1) s += __shfl_xor_sync(~0u, s, o);
    if ((tid & 31) == 0) shm[tid >> 5] = s;
    __syncthreads();
    float mu = (shm[0] + shm[1] + shm[2] + shm[3]) * (1.f / DM);

    float dx = v.x - mu, dy = v.y - mu, dz = v.z - mu, dw = v.w - mu;
    float sq = dx * dx + dy * dy + dz * dz + dw * dw;
    #pragma unroll
    for (int o = 16; o > 0; o >>= 1) sq += __shfl_xor_sync(~0u, sq, o);
    if ((tid & 31) == 0) shv[tid >> 5] = sq;
    __syncthreads();
    float var = (shv[0] + shv[1] + shv[2] + shv[3]) * (1.f / DM);
    float rstd = rsqrtf(var + 1e-5f);

    float4 gg = *(const float4*)(g + tid * 4);
    float4 bb = *(const float4*)(b + tid * 4);
    float4 o;
    o.x = dx * rstd * gg.x + bb.x;
    o.y = dy * rstd * gg.y + bb.y;
    o.z = dz * rstd * gg.z + bb.z;
    o.w = dw * rstd * gg.w + bb.w;
    *(float4*)(Y + base + tid * 4) = o;
}

// ---------------- launch ----------------
extern "C" void kernel_launch(void* const* d_in, const int* in_sizes, int n_in,
                              void* d_out, int out_size)
{
    const float* x   = (const float*)d_in[0];
    const float* Wq  = (const float*)d_in[1];
    const float* bq  = (const float*)d_in[2];
    const float* Wk  = (const float*)d_in[3];
    const float* bk  = (const float*)d_in[4];
    const float* Wv  = (const float*)d_in[5];
    const float* bv  = (const float*)d_in[6];
    const float* g1  = (const float*)d_in[7];
    const float* b1  = (const float*)d_in[8];
    const float* g2  = (const float*)d_in[9];
    const float* b2  = (const float*)d_in[10];
    const float* W1  = (const float*)d_in[11];
    const float* bf1 = (const float*)d_in[12];
    const float* W2  = (const float*)d_in[13];
    const float* bf2 = (const float*)d_in[14];
    float* out = (float*)d_out;

    float *Q, *K, *V, *S, *att, *x1, *h;
    cudaGetSymbolAddress((void**)&Q,   g_Q);
    cudaGetSymbolAddress((void**)&K,   g_K);
    cudaGetSymbolAddress((void**)&V,   g_V);
    cudaGetSymbolAddress((void**)&S,   g_S);
    cudaGetSymbolAddress((void**)&att, g_att);
    cudaGetSymbolAddress((void**)&x1,  g_x1);
    cudaGetSymbolAddress((void**)&h,   g_h);

    const float scale = 0.044194173824159216f;  // 1/sqrt(512)

    // QKV projections: [16384,512] x [512,512]
    dim3 gProj(DM / 128, NTOK / 128, 1);
    gemm128<false, false, true><<<gProj, 256>>>(x, Wq, bq, Q, NTOK, DM, DM, 1.f, 0, 0, 0);
    gemm128<false, false, true><<<gProj, 256>>>(x, Wk, bk, K, NTOK, DM, DM, 1.f, 0, 0, 0);
    gemm128<false, false, true><<<gProj, 256>>>(x, Wv, bv, V, NTOK, DM, DM, 1.f, 0, 0, 0);

    // scores = scale * Q K^T   (batched over 4)
    dim3 gScore(SQ / 128, SQ / 128, NB);
    gemm128<true, false, false><<<gScore, 256>>>(Q, K, nullptr, S, SQ, SQ, DM, scale,
        (long long)SQ * DM, (long long)SQ * DM, (long long)SQ * SQ);

    softmax4096<<<NTOK, 256>>>(S);

    // att = P V   (batched over 4)
    dim3 gPV(DM / 128, SQ / 128, NB);
    gemm128<false, false, false><<<gPV, 256>>>(S, V, nullptr, att, SQ, DM, SQ, 1.f,
        (long long)SQ * SQ, (long long)SQ * DM, (long long)SQ * DM);

    // x1 = LN(x + att)
    add_ln512<<<NTOK, 128>>>(x, att, g1, b1, x1);

    // h = relu(x1 W1 + bf1)
    dim3 gF1(DFF / 128, NTOK / 128, 1);
    gemm128<false, true, true><<<gF1, 256>>>(x1, W1, bf1, h, NTOK, DFF, DM, 1.f, 0, 0, 0);

    // ffn = h W2 + bf2   (reuse att buffer)
    dim3 gF2(DM / 128, NTOK / 128, 1);
    gemm128<false, false, true><<<gF2, 256>>>(h, W2, bf2, att, NTOK, DM, DFF, 1.f, 0, 0, 0);

    // out = LN(x1 + ffn)
    add_ln512<<<NTOK, 128>>>(x1, att, g2, b2, out);
}

// round 3
// speedup vs baseline: 6.8231x; 6.8231x over previous
#include <cuda_runtime.h>
#include <cuda_fp16.h>
#include <cstdint>
#include <math.h>

typedef __half half_t;

#define NTOK 16384
#define DM   512
#define DFF  2048
#define SQ   4096
#define NB   4

// ---------------- device scratch (no allocations) ----------------
__device__ half_t g_xh [NTOK * DM];
__device__ half_t g_Wqt[DM * DM];     // [out][in]
__device__ half_t g_Wkt[DM * DM];
__device__ half_t g_Wvt[DM * DM];
__device__ half_t g_W1t[DFF * DM];    // [2048][512]
__device__ half_t g_W2t[DM * DFF];    // [512][2048]
__device__ half_t g_Q  [NTOK * DM];
__device__ half_t g_K  [NTOK * DM];
__device__ half_t g_Vn [NTOK * DM];   // V normal layout
__device__ half_t g_Vt [NB * DM * SQ];// V^T per batch [b][d][tok]
__device__ half_t g_S  [67108864];    // 4*4096*4096, reused as P after softmax
__device__ half_t g_h  [NTOK * DFF];
__device__ half_t g_x1h[NTOK * DM];
__device__ float  g_att[NTOK * DM];   // also ffn output
__device__ float  g_x1 [NTOK * DM];

// ---------------- smem addr helper ----------------
__device__ __forceinline__ uint32_t cvta_smem(const void* p) {
    uint32_t a;
    asm("{ .reg .u64 t; cvta.to.shared.u64 t, %1; cvt.u32.u64 %0, t; }" : "=r"(a) : "l"(p));
    return a;
}
// swizzled byte offset inside a [128 rows x 32 half] tile (64B rows, 4x16B units)
__device__ __forceinline__ uint32_t swz(int row, int cu) {
    return (uint32_t)(row * 64 + ((cu ^ ((row >> 1) & 3)) << 4));
}
__device__ __forceinline__ void cp_async16(uint32_t dst, const void* src) {
    asm volatile("cp.async.cg.shared.global [%0], [%1], 16;" :: "r"(dst), "l"(src));
}
__device__ __forceinline__ void ldm_x4(uint32_t addr, uint32_t& r0, uint32_t& r1,
                                       uint32_t& r2, uint32_t& r3) {
    asm volatile("ldmatrix.sync.aligned.m8n8.x4.shared.b16 {%0,%1,%2,%3}, [%4];"
                 : "=r"(r0), "=r"(r1), "=r"(r2), "=r"(r3) : "r"(addr));
}
__device__ __forceinline__ void mma16816(float& d0, float& d1, float& d2, float& d3,
                                         uint32_t a0, uint32_t a1, uint32_t a2, uint32_t a3,
                                         uint32_t b0, uint32_t b1) {
    asm volatile("mma.sync.aligned.m16n8k16.row.col.f32.f16.f16.f32 "
                 "{%0,%1,%2,%3}, {%4,%5,%6,%7}, {%8,%9}, {%0,%1,%2,%3};"
                 : "+f"(d0), "+f"(d1), "+f"(d2), "+f"(d3)
                 : "r"(a0), "r"(a1), "r"(a2), "r"(a3), "r"(b0), "r"(b1));
}

// ---------------- fp16 HMMA GEMM: C = alpha * A[M,K] * B[N,K]^T (+bias)(relu) ----------------
// OUT: 0 = fp32, 1 = fp16.  M,N mult of 128, K mult of 32.
#define NSTAGE 3
#define STAGEB 16384          // A tile 8KB + B tile 8KB

template<int OUT, bool BIAS, bool RELU>
__global__ __launch_bounds__(256, 2)
void hgemm(const half_t* __restrict__ A, const half_t* __restrict__ B,
           const float* __restrict__ bias, void* __restrict__ Cv,
           int M, int N, int K, float alpha,
           long long sA, long long sB, long long sC)
{
    __shared__ __align__(16) char smbuf[NSTAGE * STAGEB];
    const uint32_t smBase = cvta_smem(smbuf);

    const int tid  = threadIdx.x;
    const int lane = tid & 31;
    const int warp = tid >> 5;
    const int wm = warp >> 2, wn = warp & 3;       // 2 x 4 warps, warp tile 64x32
    const int rowBase = blockIdx.y * 128;
    const int colBase = blockIdx.x * 128;

    A += (long long)blockIdx.z * sA;
    B += (long long)blockIdx.z * sB;

    // per-thread cp.async pattern: two rows (r, r+64), one 16B unit each
    const int lr = tid >> 2;        // 0..63
    const int lc = tid & 3;         // 0..3
    const uint32_t dA0 = swz(lr, lc), dA1 = swz(lr + 64, lc);
    const int kIters = K >> 5;

    float acc[4][4][4];
    #pragma unroll
    for (int i = 0; i < 4; ++i)
        #pragma unroll
        for (int j = 0; j < 4; ++j)
            #pragma unroll
            for (int r = 0; r < 4; ++r) acc[i][j][r] = 0.f;

    auto issue = [&](int it) {
        if (it < kIters) {
            const int k0 = it << 5;
            const uint32_t sa = smBase + (it % NSTAGE) * STAGEB;
            const uint32_t sb = sa + 8192;
            const half_t* gA = A + (long long)(rowBase + lr) * K + k0 + lc * 8;
            const half_t* gB = B + (long long)(colBase + lr) * K + k0 + lc * 8;
            cp_async16(sa + dA0, gA);
            cp_async16(sa + dA1, gA + (long long)64 * K);
            cp_async16(sb + dA0, gB);
            cp_async16(sb + dA1, gB + (long long)64 * K);
        }
        asm volatile("cp.async.commit_group;");
    };

    issue(0);
    issue(1);

    // fragment address components
    const int aRow0 = wm * 64 + (lane & 15);
    const int aCuHi = lane >> 4;                        // 0/1
    const int bRow0 = wn * 32 + (lane & 7) + ((lane >> 4) << 3);
    const int bCuHi = (lane >> 3) & 1;

    for (int it = 0; it < kIters; ++it) {
        asm volatile("cp.async.wait_group 1;");
        __syncthreads();
        issue(it + 2);

        const uint32_t sa = smBase + (it % NSTAGE) * STAGEB;
        const uint32_t sb = sa + 8192;

        #pragma unroll
        for (int ks = 0; ks < 2; ++ks) {
            uint32_t af[4][4], bf[4][2];
            #pragma unroll
            for (int mt = 0; mt < 4; ++mt)
                ldm_x4(sa + swz(aRow0 + mt * 16, ks * 2 + aCuHi),
                       af[mt][0], af[mt][1], af[mt][2], af[mt][3]);
            #pragma unroll
            for (int np = 0; np < 2; ++np) {
                uint32_t r0, r1, r2, r3;
                ldm_x4(sb + swz(bRow0 + np * 16, ks * 2 + bCuHi), r0, r1, r2, r3);
                bf[np * 2][0] = r0; bf[np * 2][1] = r1;
                bf[np * 2 + 1][0] = r2; bf[np * 2 + 1][1] = r3;
            }
            #pragma unroll
            for (int mt = 0; mt < 4; ++mt)
                #pragma unroll
                for (int nt = 0; nt < 4; ++nt)
                    mma16816(acc[mt][nt][0], acc[mt][nt][1], acc[mt][nt][2], acc[mt][nt][3],
                             af[mt][0], af[mt][1], af[mt][2], af[mt][3],
                             bf[nt][0], bf[nt][1]);
        }
        __syncthreads();
    }

    // epilogue
    const long long cz = (long long)blockIdx.z * sC;
    #pragma unroll
    for (int mt = 0; mt < 4; ++mt) {
        const int rA = rowBase + wm * 64 + mt * 16 + (lane >> 2);
        #pragma unroll
        for (int nt = 0; nt < 4; ++nt) {
            const int cc = colBase + wn * 32 + nt * 8 + 2 * (lane & 3);
            float v0 = acc[mt][nt][0] * alpha, v1 = acc[mt][nt][1] * alpha;
            float v2 = acc[mt][nt][2] * alpha, v3 = acc[mt][nt][3] * alpha;
            if (BIAS) {
                float2 bv = *(const float2*)(bias + cc);
                v0 += bv.x; v1 += bv.y; v2 += bv.x; v3 += bv.y;
            }
            if (RELU) {
                v0 = fmaxf(v0, 0.f); v1 = fmaxf(v1, 0.f);
                v2 = fmaxf(v2, 0.f); v3 = fmaxf(v3, 0.f);
            }
            if (OUT == 1) {
                half_t* C = (half_t*)Cv;
                *(half2*)(C + cz + (long long)rA * N + cc)       = __floats2half2_rn(v0, v1);
                *(half2*)(C + cz + (long long)(rA + 8) * N + cc) = __floats2half2_rn(v2, v3);
            } else {
                float* C = (float*)Cv;
                *(float2*)(C + cz + (long long)rA * N + cc)       = make_float2(v0, v1);
                *(float2*)(C + cz + (long long)(rA + 8) * N + cc) = make_float2(v2, v3);
            }
        }
    }
}

// ---------------- fp32 -> fp16 convert ----------------
__global__ __launch_bounds__(256)
void cvt_half(const float* __restrict__ in, half_t* __restrict__ out, int n4)
{
    int i = blockIdx.x * 256 + threadIdx.x;
    if (i >= n4) return;
    float4 v = ((const float4*)in)[i];
    union { uint2 u; half_t h[4]; } o;
    o.h[0] = __float2half_rn(v.x); o.h[1] = __float2half_rn(v.y);
    o.h[2] = __float2half_rn(v.z); o.h[3] = __float2half_rn(v.w);
    ((uint2*)out)[i] = o.u;
}

// ---------------- transpose + convert: W[K,N] fp32 -> Wt[N,K] fp16 ----------------
__global__ __launch_bounds__(256)
void transpose_cvt(const float* __restrict__ W, half_t* __restrict__ Wt, int K, int N)
{
    __shared__ float t[32][33];
    int kb = blockIdx.y * 32, nb = blockIdx.x * 32;
    int tx = threadIdx.x, ty = threadIdx.y;  // (32,8)
    #pragma unroll
    for (int i = 0; i < 32; i += 8)
        t[ty + i][tx] = W[(size_t)(kb + ty + i) * N + nb + tx];
    __syncthreads();
    #pragma unroll
    for (int i = 0; i < 32; i += 8)
        Wt[(size_t)(nb + ty + i) * K + kb + tx] = __float2half_rn(t[tx][ty + i]);
}

// ---------------- V transpose: fp16 [16384,512] -> [b][512][4096] ----------------
__global__ __launch_bounds__(256)
void transposeV(const half_t* __restrict__ V, half_t* __restrict__ Vt)
{
    __shared__ half_t t[32][33];
    int dB = blockIdx.x * 32, tokB = blockIdx.y * 32;
    int tx = threadIdx.x, ty = threadIdx.y;  // (32,8)
    #pragma unroll
    for (int i = 0; i < 32; i += 8)
        t[ty + i][tx] = V[(size_t)(tokB + ty + i) * DM + dB + tx];
    __syncthreads();
    const int b = tokB >> 12;
    const int tokin = tokB & (SQ - 1);
    #pragma unroll
    for (int i = 0; i < 32; i += 8)
        Vt[(size_t)b * DM * SQ + (size_t)(dB + ty + i) * SQ + tokin + tx] = t[tx][ty + i];
}

// ---------------- softmax over 4096, fp16 in-place ----------------
__global__ __launch_bounds__(256)
void softmax_h(half_t* __restrict__ S)
{
    half_t* p = S + (long long)blockIdx.x * SQ;
    const int tid = threadIdx.x;
    union U { uint4 q; half_t h[8]; };
    U u[2];
    u[0].q = ((const uint4*)p)[tid];
    u[1].q = ((const uint4*)p)[tid + 256];

    float f[16];
    float mx = -1e30f;
    #pragma unroll
    for (int i = 0; i < 16; ++i) {
        f[i] = __half2float(u[i >> 3].h[i & 7]);
        mx = fmaxf(mx, f[i]);
    }
    __shared__ float sh[8];
    #pragma unroll
    for (int o = 16; o > 0; o >>= 1) mx = fmaxf(mx, __shfl_xor_sync(~0u, mx, o));
    if ((tid & 31) == 0) sh[tid >> 5] = mx;
    __syncthreads();
    mx = sh[0];
    #pragma unroll
    for (int w = 1; w < 8; ++w) mx = fmaxf(mx, sh[w]);
    __syncthreads();

    float sum = 0.f;
    #pragma unroll
    for (int i = 0; i < 16; ++i) { f[i] = __expf(f[i] - mx); sum += f[i]; }
    #pragma unroll
    for (int o = 16; o > 0; o >>= 1) sum += __shfl_xor_sync(~0u, sum, o);
    if ((tid & 31) == 0) sh[tid >> 5] = sum;
    __syncthreads();
    sum = 0.f;
    #pragma unroll
    for (int w = 0; w < 8; ++w) sum += sh[w];
    const float inv = 1.f / sum;

    #pragma unroll
    for (int i = 0; i < 16; ++i)
        u[i >> 3].h[i & 7] = __float2half_rn(f[i] * inv);
    ((uint4*)p)[tid]       = u[0].q;
    ((uint4*)p)[tid + 256] = u[1].q;
}

// ---------------- residual add + LayerNorm(512) ----------------
template<bool EMIT_HALF>
__global__ __launch_bounds__(128)
void add_ln512(const float* __restrict__ X, const float* __restrict__ R,
               const float* __restrict__ g, const float* __restrict__ b,
               float* __restrict__ Y, half_t* __restrict__ Yh)
{
    const int tid = threadIdx.x;
    const long long base = (long long)blockIdx.x * DM;
    float4 v = *(const float4*)(X + base + tid * 4);
    float4 r = *(const float4*)(R + base + tid * 4);
    v.x += r.x; v.y += r.y; v.z += r.z; v.w += r.w;

    __shared__ float shm[4], shv[4];
    float s = v.x + v.y + v.z + v.w;
    #pragma unroll
    for (int o = 16; o > 0; o >>= 1) s += __shfl_xor_sync(~0u, s, o);
    if ((tid & 31) == 0) shm[tid >> 5] = s;
    __syncthreads();
    float mu = (shm[0] + shm[1] + shm[2] + shm[3]) * (1.f / DM);

    float dx = v.x - mu, dy = v.y - mu, dz = v.z - mu, dw = v.w - mu;
    float sq = dx * dx + dy * dy + dz * dz + dw * dw;
    #pragma unroll
    for (int o = 16; o > 0; o >>= 1) sq += __shfl_xor_sync(~0u, sq, o);
    if ((tid & 31) == 0) shv[tid >> 5] = sq;
    __syncthreads();
    float var = (shv[0] + shv[1] + shv[2] + shv[3]) * (1.f / DM);
    float rstd = rsqrtf(var + 1e-5f);

    float4 gg = *(const float4*)(g + tid * 4);
    float4 bb = *(const float4*)(b + tid * 4);
    float4 o;
    o.x = dx * rstd * gg.x + bb.x;
    o.y = dy * rstd * gg.y + bb.y;
    o.z = dz * rstd * gg.z + bb.z;
    o.w = dw * rstd * gg.w + bb.w;
    *(float4*)(Y + base + tid * 4) = o;
    if (EMIT_HALF) {
        union { uint2 u; half_t h[4]; } H;
        H.h[0] = __float2half_rn(o.x); H.h[1] = __float2half_rn(o.y);
        H.h[2] = __float2half_rn(o.z); H.h[3] = __float2half_rn(o.w);
        ((uint2*)(Yh + base))[tid] = H.u;
    }
}

// ---------------- launch ----------------
extern "C" void kernel_launch(void* const* d_in, const int* in_sizes, int n_in,
                              void* d_out, int out_size)
{
    const float* x   = (const float*)d_in[0];
    const float* Wq  = (const float*)d_in[1];
    const float* bq  = (const float*)d_in[2];
    const float* Wk  = (const float*)d_in[3];
    const float* bk  = (const float*)d_in[4];
    const float* Wv  = (const float*)d_in[5];
    const float* bv  = (const float*)d_in[6];
    const float* g1  = (const float*)d_in[7];
    const float* b1  = (const float*)d_in[8];
    const float* g2  = (const float*)d_in[9];
    const float* b2  = (const float*)d_in[10];
    const float* W1  = (const float*)d_in[11];
    const float* bf1 = (const float*)d_in[12];
    const float* W2  = (const float*)d_in[13];
    const float* bf2 = (const float*)d_in[14];
    float* out = (float*)d_out;

    half_t *xh, *Wqt, *Wkt, *Wvt, *W1t, *W2t, *Q, *K, *Vn, *Vt, *S, *h, *x1h;
    float *att, *x1;
    cudaGetSymbolAddress((void**)&xh,  g_xh);
    cudaGetSymbolAddress((void**)&Wqt, g_Wqt);
    cudaGetSymbolAddress((void**)&Wkt, g_Wkt);
    cudaGetSymbolAddress((void**)&Wvt, g_Wvt);
    cudaGetSymbolAddress((void**)&W1t, g_W1t);
    cudaGetSymbolAddress((void**)&W2t, g_W2t);
    cudaGetSymbolAddress((void**)&Q,   g_Q);
    cudaGetSymbolAddress((void**)&K,   g_K);
    cudaGetSymbolAddress((void**)&Vn,  g_Vn);
    cudaGetSymbolAddress((void**)&Vt,  g_Vt);
    cudaGetSymbolAddress((void**)&S,   g_S);
    cudaGetSymbolAddress((void**)&h,   g_h);
    cudaGetSymbolAddress((void**)&x1h, g_x1h);
    cudaGetSymbolAddress((void**)&att, g_att);
    cudaGetSymbolAddress((void**)&x1,  g_x1);

    const float scale = 0.044194173824159216f;  // 1/sqrt(512)
    dim3 tb(32, 8);

    // 0) conversions
    cvt_half<<<(NTOK * DM / 4 + 255) / 256, 256>>>(x, xh, NTOK * DM / 4);
    transpose_cvt<<<dim3(DM / 32, DM / 32),  tb>>>(Wq, Wqt, DM, DM);
    transpose_cvt<<<dim3(DM / 32, DM / 32),  tb>>>(Wk, Wkt, DM, DM);
    transpose_cvt<<<dim3(DM / 32, DM / 32),  tb>>>(Wv, Wvt, DM, DM);
    transpose_cvt<<<dim3(DFF / 32, DM / 32), tb>>>(W1, W1t, DM, DFF);
    transpose_cvt<<<dim3(DM / 32, DFF / 32), tb>>>(W2, W2t, DFF, DM);

    // 1) QKV projections
    dim3 gProj(DM / 128, NTOK / 128, 1);
    hgemm<1, true, false><<<gProj, 256>>>(xh, Wqt, bq, Q,  NTOK, DM, DM, 1.f, 0, 0, 0);
    hgemm<1, true, false><<<gProj, 256>>>(xh, Wkt, bk, K,  NTOK, DM, DM, 1.f, 0, 0, 0);
    hgemm<1, true, false><<<gProj, 256>>>(xh, Wvt, bv, Vn, NTOK, DM, DM, 1.f, 0, 0, 0);
    transposeV<<<dim3(DM / 32, NTOK / 32), tb>>>(Vn, Vt);

    // 2) scores = scale * Q K^T (fp16 out), batched
    dim3 gScore(SQ / 128, SQ / 128, NB);
    hgemm<1, false, false><<<gScore, 256>>>(Q, K, nullptr, S, SQ, SQ, DM, scale,
        (long long)SQ * DM, (long long)SQ * DM, (long long)SQ * SQ);

    // 3) softmax in place (S -> P)
    softmax_h<<<NTOK, 256>>>(S);

    // 4) att = P V (fp32 out), batched
    dim3 gPV(DM / 128, SQ / 128, NB);
    hgemm<0, false, false><<<gPV, 256>>>(S, Vt, nullptr, att, SQ, DM, SQ, 1.f,
        (long long)SQ * SQ, (long long)DM * SQ, (long long)SQ * DM);

    // 5) x1 = LN(x + att), emit fp16
    add_ln512<true><<<NTOK, 128>>>(x, att, g1, b1, x1, x1h);

    // 6) h = relu(x1 W1 + bf1) fp16
    dim3 gF1(DFF / 128, NTOK / 128, 1);
    hgemm<1, true, true><<<gF1, 256>>>(x1h, W1t, bf1, h, NTOK, DFF, DM, 1.f, 0, 0, 0);

    // 7) ffn = h W2 + bf2 fp32 (reuse att)
    dim3 gF2(DM / 128, NTOK / 128, 1);
    hgemm<0, true, false><<<gF2, 256>>>(h, W2t, bf2, att, NTOK, DM, DFF, 1.f, 0, 0, 0);

    // 8) out = LN(x1 + ffn)
    add_ln512<false><<<NTOK, 128>>>(x1, att, g2, b2, out, nullptr);
}